// round 2
// baseline (speedup 1.0000x reference)
#include <cuda_runtime.h>
#include <cstddef>

// ContrastMemory for GB300.
// d_out layout (float32, reference return order):
//   [0, H)          out_v1   = exp((memory_v2[idx] . v1)/T) / Z_v1
//   [H, 2H)         out_v2   = exp((memory_v1[idx] . v2)/T) / Z_v2
//   [2H, 2H+ND)     new_memory_v1
//   [2H+ND, 2H+2ND) new_memory_v2
// where H = B*(K+1), ND = N*D.

#define T_INV 14.2857142857142857f   // 1/0.07 (temperature)
#define MOM   0.5f

__device__ double g_sum[2];   // [0]: sum of raw out_v1 exps, [1]: out_v2

__global__ void zero_sums_kernel() {
    if (threadIdx.x < 2) g_sum[threadIdx.x] = 0.0;
}

// One warp per dot product, 2 dots in flight per iteration.
// D is assumed 128 (32 lanes x float4).
__global__ void dot_kernel(const float* __restrict__ v1,
                           const float* __restrict__ v2,
                           const int*   __restrict__ idx,
                           const float* __restrict__ mem1,
                           const float* __restrict__ mem2,
                           float* __restrict__ out,
                           int H, int KP1)
{
    const int warpsPerBlock = blockDim.x >> 5;
    const int warpInBlock   = threadIdx.x >> 5;
    const int lane          = threadIdx.x & 31;
    const int gwarp         = blockIdx.x * warpsPerBlock + warpInBlock;
    const int totalWarps    = gridDim.x * warpsPerBlock;
    const int total         = 2 * H;

    float local0 = 0.0f, local1 = 0.0f;   // lane-0 accumulators

    // two dots per iteration for memory-level parallelism
    for (int dot = gwarp; dot < total; dot += 2 * totalWarps) {
        const int dotB = dot + totalWarps;
        const bool haveB = (dotB < total);

        // --- dot A addresses ---
        const int  halfA = (dot >= H);
        const int  d2A   = halfA ? (dot - H) : dot;
        const int  bA    = d2A / KP1;
        const int  kA    = d2A - bA * KP1;
        const int  rA    = __ldg(&idx[bA * KP1 + kA]);
        const float4* rowA = reinterpret_cast<const float4*>(
                                 (halfA ? mem1 : mem2) + (size_t)rA * 128) + lane;
        const float4* vvA  = reinterpret_cast<const float4*>(
                                 (halfA ? v2 : v1) + (size_t)bA * 128) + lane;

        // --- dot B addresses ---
        int halfB = 0, bB = 0;
        const float4* rowB = rowA;
        const float4* vvB  = vvA;
        if (haveB) {
            halfB = (dotB >= H);
            const int d2B = halfB ? (dotB - H) : dotB;
            bB = d2B / KP1;
            const int kB = d2B - bB * KP1;
            const int rB = __ldg(&idx[bB * KP1 + kB]);
            rowB = reinterpret_cast<const float4*>(
                       (halfB ? mem1 : mem2) + (size_t)rB * 128) + lane;
            vvB  = reinterpret_cast<const float4*>(
                       (halfB ? v2 : v1) + (size_t)bB * 128) + lane;
        }

        // issue both gathers before either reduction
        const float4 aA = *rowA;
        const float4 cA = *vvA;
        const float4 aB = *rowB;
        const float4 cB = *vvB;

        float sA = aA.x * cA.x + aA.y * cA.y + aA.z * cA.z + aA.w * cA.w;
        float sB = aB.x * cB.x + aB.y * cB.y + aB.z * cB.z + aB.w * cB.w;

        #pragma unroll
        for (int o = 16; o > 0; o >>= 1) {
            sA += __shfl_xor_sync(0xffffffffu, sA, o);
            sB += __shfl_xor_sync(0xffffffffu, sB, o);
        }

        if (lane == 0) {
            const float eA = expf(sA * T_INV);
            out[dot] = eA;
            if (halfA) local1 += eA; else local0 += eA;
            if (haveB) {
                const float eB = expf(sB * T_INV);
                out[dotB] = eB;
                if (halfB) local1 += eB; else local0 += eB;
            }
        }
    }

    // block reduce -> one double atomic per block per half
    __shared__ float sh0[32], sh1[32];
    if (lane == 0) { sh0[warpInBlock] = local0; sh1[warpInBlock] = local1; }
    __syncthreads();
    if (threadIdx.x == 0) {
        float a = 0.0f, b = 0.0f;
        for (int w = 0; w < warpsPerBlock; ++w) { a += sh0[w]; b += sh1[w]; }
        atomicAdd(&g_sum[0], (double)a);
        atomicAdd(&g_sum[1], (double)b);
    }
}

// Streaming pass: scale the two out halves by 1/Z, and copy both memory banks
// into the output regions. float4 granularity.
__global__ void finalize_kernel(float4* __restrict__ out4,
                                const float4* __restrict__ mem1,
                                const float4* __restrict__ mem2,
                                int Hv,     // H/4
                                int NDv,    // N*D/4
                                int H, long long Nll)
{
    const int i = blockIdx.x * blockDim.x + threadIdx.x;
    const int total = 2 * Hv + 2 * NDv;
    if (i >= total) return;

    if (i < 2 * Hv) {
        // scale = H / (sum * N)   since Z = (sum/H) * N
        const double s = (i < Hv) ? g_sum[0] : g_sum[1];
        const float scale = (float)((double)H / (s * (double)Nll));
        float4 v = out4[i];
        v.x *= scale; v.y *= scale; v.z *= scale; v.w *= scale;
        out4[i] = v;
    } else if (i < 2 * Hv + NDv) {
        out4[i] = mem1[i - 2 * Hv];
    } else {
        out4[i] = mem2[i - 2 * Hv - NDv];
    }
}

// Momentum-blend + l2-normalize + scatter into the already-copied output
// memory. grid = (B, 2); block = D (=128) threads.
__global__ void update_kernel(const float* __restrict__ v1,
                              const float* __restrict__ v2,
                              const float* __restrict__ mem1,
                              const float* __restrict__ mem2,
                              const int*   __restrict__ y,
                              float* __restrict__ outmem1,
                              float* __restrict__ outmem2,
                              int D)
{
    const int i     = blockIdx.x;
    const int which = blockIdx.y;
    const int t     = threadIdx.x;
    const int lane  = t & 31;

    const float* v      = which ? v2      : v1;
    const float* mem    = which ? mem2    : mem1;
    float*       outmem = which ? outmem2 : outmem1;

    const int row = __ldg(&y[i]);
    const float u = MOM * mem[(size_t)row * D + t] + (1.0f - MOM) * v[(size_t)i * D + t];

    float ss = u * u;
    #pragma unroll
    for (int o = 16; o > 0; o >>= 1)
        ss += __shfl_xor_sync(0xffffffffu, ss, o);

    __shared__ float sh[32];
    if (lane == 0) sh[t >> 5] = ss;
    __syncthreads();

    float tot = 0.0f;
    const int nwarps = blockDim.x >> 5;
    for (int w = 0; w < nwarps; ++w) tot += sh[w];

    outmem[(size_t)row * D + t] = u * rsqrtf(tot);
}

extern "C" void kernel_launch(void* const* d_in, const int* in_sizes, int n_in,
                              void* d_out, int out_size)
{
    const float* v1   = (const float*)d_in[0];
    const float* v2   = (const float*)d_in[1];
    const int*   idx  = (const int*)  d_in[2];
    const int*   y    = (const int*)  d_in[3];
    const float* mem1 = (const float*)d_in[4];
    const float* mem2 = (const float*)d_in[5];

    const int B   = in_sizes[3];          // 128
    const int D   = in_sizes[0] / B;      // 128
    const int KP1 = in_sizes[2] / B;      // 4097
    const int N   = in_sizes[4] / D;      // 100000
    const int H   = B * KP1;              // 524416
    const int ND  = N * D;                // 12800000

    float* out = (float*)d_out;
    float* outmem1 = out + 2 * (size_t)H;
    float* outmem2 = outmem1 + (size_t)ND;

    zero_sums_kernel<<<1, 32>>>();

    dot_kernel<<<1998, 256>>>(v1, v2, idx, mem1, mem2, out, H, KP1);

    const int Hv  = H / 4;
    const int NDv = ND / 4;
    const int totalVec = 2 * Hv + 2 * NDv;
    const int fblocks = (totalVec + 255) / 256;
    finalize_kernel<<<fblocks, 256>>>((float4*)d_out,
                                      (const float4*)mem1, (const float4*)mem2,
                                      Hv, NDv, H, (long long)N);

    update_kernel<<<dim3(B, 2), D>>>(v1, v2, mem1, mem2, y, outmem1, outmem2, D);
}

// round 4
// speedup vs baseline: 1.5516x; 1.5516x over previous
#include <cuda_runtime.h>
#include <cstddef>

// ContrastMemory for GB300.
// d_out layout (float32, reference return order):
//   [0, H)          out_v1   = exp((memory_v2[idx] . v1)/T) / Z_v1
//   [H, 2H)         out_v2   = exp((memory_v1[idx] . v2)/T) / Z_v2
//   [2H, 2H+ND)     new_memory_v1
//   [2H+ND, 2H+2ND) new_memory_v2

#define T_INV 14.2857142857142857f   // 1/0.07
#define MOM   0.5f

__device__ double g_sum[2];   // [0]: raw out_v1 exp sum, [1]: out_v2

__global__ void zero_sums_kernel() {
    if (threadIdx.x < 2) g_sum[threadIdx.x] = 0.0;
}

// Fused: gathered dot products (4 per warp per iteration, 8-lane groups)
// interleaved with the memory-bank copy-through (DRAM stream overlaps L2 gathers).
__global__ void __launch_bounds__(256) fused_kernel(
        const float* __restrict__ v1,
        const float* __restrict__ v2,
        const int*   __restrict__ idx,
        const float* __restrict__ mem1,
        const float* __restrict__ mem2,
        float* __restrict__ out,
        float* __restrict__ outmem1,
        float* __restrict__ outmem2,
        int H, int KP1, float invKP1,
        int NG,            // number of 4-dot groups = 2H/4
        int NC1, int NC)   // copy chunks per bank, total (2*NC1)
{
    const int warpsPerBlock = blockDim.x >> 5;
    const int warpInBlock   = threadIdx.x >> 5;
    const int lane          = threadIdx.x & 31;
    const int g             = lane >> 3;     // dot-group within warp (0..3)
    const int sl            = lane & 7;      // sub-lane within group
    const int gwarp         = blockIdx.x * warpsPerBlock + warpInBlock;
    const int totalWarps    = gridDim.x * warpsPerBlock;

    float local0 = 0.0f, local1 = 0.0f;

    for (int it = 0; ; ++it) {
        const int G = gwarp + it * totalWarps;   // dot-group id
        const int C = G;                         // copy-chunk id (same stride)
        const bool doDot  = (G < NG);
        const bool doCopy = (C < NC);
        if (!doDot && !doCopy) break;

        // ---- issue copy load early (DRAM latency overlaps dot work) ----
        float4 cval;
        float4* cdst = 0;
        if (doCopy) {
            const float4* csrc;
            if (C < NC1) {
                csrc = reinterpret_cast<const float4*>(mem1) + (size_t)C * 32;
                cdst = reinterpret_cast<float4*>(outmem1)    + (size_t)C * 32;
            } else {
                const int C2 = C - NC1;
                csrc = reinterpret_cast<const float4*>(mem2) + (size_t)C2 * 32;
                cdst = reinterpret_cast<float4*>(outmem2)    + (size_t)C2 * 32;
            }
            cval = csrc[lane];   // normal load: warms L2 with the bank row
        }

        // ---- 4 dots per warp; this lane works on dot 4G+g ----
        if (doDot) {
            const int dot  = 4 * G + g;
            const int half = (dot >= H);                 // 0: mem2.v1, 1: mem1.v2
            const int d2   = half ? (dot - H) : dot;

            // b = d2 / KP1 via float reciprocal + exact correction
            int b = __float2int_rz(__int2float_rn(d2) * invKP1);
            int rem = d2 - b * KP1;
            if (rem < 0)          { b--; }
            else if (rem >= KP1)  { b++; }

            const int r = __ldg(&idx[d2]);

            const float4* row = reinterpret_cast<const float4*>(
                                    (half ? mem1 : mem2) + (size_t)r * 128);
            const float4* vv  = reinterpret_cast<const float4*>(
                                    (half ? v2 : v1) + (size_t)b * 128);

            float s = 0.0f;
            #pragma unroll
            for (int j = 0; j < 4; ++j) {
                const float4 a = row[sl + 8 * j];
                const float4 c = vv[sl + 8 * j];
                s += a.x * c.x + a.y * c.y + a.z * c.z + a.w * c.w;
            }
            // reduce across the 8-lane group (stays within group: bits 0..2)
            s += __shfl_xor_sync(0xffffffffu, s, 1);
            s += __shfl_xor_sync(0xffffffffu, s, 2);
            s += __shfl_xor_sync(0xffffffffu, s, 4);

            if (sl == 0) {
                const float e = __expf(s * T_INV);
                __stcs(&out[dot], e);
                if (half) local1 += e; else local0 += e;
            }
        }

        // ---- copy store (evict-first: don't pollute L2) ----
        if (doCopy) __stcs(&cdst[lane], cval);
    }

    // warp reduce locals (non-sl0 lanes hold 0)
    #pragma unroll
    for (int o = 16; o > 0; o >>= 1) {
        local0 += __shfl_xor_sync(0xffffffffu, local0, o);
        local1 += __shfl_xor_sync(0xffffffffu, local1, o);
    }
    __shared__ float sh0[8], sh1[8];
    if (lane == 0) { sh0[warpInBlock] = local0; sh1[warpInBlock] = local1; }
    __syncthreads();
    if (threadIdx.x == 0) {
        float a = 0.0f, b = 0.0f;
        for (int w = 0; w < warpsPerBlock; ++w) { a += sh0[w]; b += sh1[w]; }
        atomicAdd(&g_sum[0], (double)a);
        atomicAdd(&g_sum[1], (double)b);
    }
}

// Epilogue: scale the score halves by 1/Z, and momentum-update the B rows in
// the already-copied output memory banks.
__global__ void __launch_bounds__(256) finish_kernel(
        float4* __restrict__ out4,
        int Hv2,   // 2H/4 float4 items
        int Hv,    // H/4
        int H, long long Nll,
        const float* __restrict__ v1,
        const float* __restrict__ v2,
        const float* __restrict__ mem1,
        const float* __restrict__ mem2,
        const int*   __restrict__ y,
        float* __restrict__ outmem1,
        float* __restrict__ outmem2,
        int scaleBlocks)
{
    if ((int)blockIdx.x < scaleBlocks) {
        const int i = blockIdx.x * blockDim.x + threadIdx.x;
        if (i < Hv2) {
            const double s = (i < Hv) ? g_sum[0] : g_sum[1];
            const float scale = (float)((double)H / (s * (double)Nll));
            float4 v = out4[i];
            v.x *= scale; v.y *= scale; v.z *= scale; v.w *= scale;
            out4[i] = v;
        }
        return;
    }

    // update part: 2 (row, view) pairs per block
    const int ub    = blockIdx.x - scaleBlocks;   // 0..B-1
    const int which = threadIdx.x >> 7;           // 0/1
    const int t     = threadIdx.x & 127;          // feature index
    const int lane  = threadIdx.x & 31;
    const int w128  = (threadIdx.x >> 5) & 3;     // warp within 128-thread half

    const float* v      = which ? v2      : v1;
    const float* mem    = which ? mem2    : mem1;
    float*       outmem = which ? outmem2 : outmem1;

    const int row = __ldg(&y[ub]);
    const float u = MOM * mem[(size_t)row * 128 + t] + (1.0f - MOM) * v[(size_t)ub * 128 + t];

    float ss = u * u;
    #pragma unroll
    for (int o = 16; o > 0; o >>= 1)
        ss += __shfl_xor_sync(0xffffffffu, ss, o);

    __shared__ float sh[2][4];
    if (lane == 0) sh[which][w128] = ss;
    __syncthreads();

    const float tot = sh[which][0] + sh[which][1] + sh[which][2] + sh[which][3];
    outmem[(size_t)row * 128 + t] = u * rsqrtf(tot);
}

extern "C" void kernel_launch(void* const* d_in, const int* in_sizes, int n_in,
                              void* d_out, int out_size)
{
    const float* v1   = (const float*)d_in[0];
    const float* v2   = (const float*)d_in[1];
    const int*   idx  = (const int*)  d_in[2];
    const int*   y    = (const int*)  d_in[3];
    const float* mem1 = (const float*)d_in[4];
    const float* mem2 = (const float*)d_in[5];

    const int B   = in_sizes[3];          // 128
    const int D   = in_sizes[0] / B;      // 128
    const int KP1 = in_sizes[2] / B;      // 4097
    const int N   = in_sizes[4] / D;      // 100000
    const int H   = B * KP1;              // 524416
    const int ND  = N * D;                // 12800000

    float* out = (float*)d_out;
    float* outmem1 = out + 2 * (size_t)H;
    float* outmem2 = outmem1 + (size_t)ND;

    const int NG  = (2 * H) / 4;          // dot groups (2H divisible by 4)
    const int NC1 = ND / 128;             // 512B chunks per bank (= N rows)
    const int NC  = 2 * NC1;
    const float invKP1 = 1.0f / (float)KP1;

    zero_sums_kernel<<<1, 32>>>();

    fused_kernel<<<1998, 256>>>(v1, v2, idx, mem1, mem2,
                                out, outmem1, outmem2,
                                H, KP1, invKP1, NG, NC1, NC);

    const int Hv  = H / 4;
    const int Hv2 = 2 * Hv;
    const int scaleBlocks = (Hv2 + 255) / 256;
    finish_kernel<<<scaleBlocks + B, 256>>>((float4*)d_out, Hv2, Hv, H, (long long)N,
                                            v1, v2, mem1, mem2, y,
                                            outmem1, outmem2, scaleBlocks);
}

// round 5
// speedup vs baseline: 1.6456x; 1.0606x over previous
#include <cuda_runtime.h>
#include <cstddef>

// ContrastMemory for GB300 — row-inverted gather.
// d_out layout (float32):
//   [0, H)          out_v1   = exp((memory_v2[idx] . v1)/T) / Z_v1
//   [H, 2H)         out_v2   = exp((memory_v1[idx] . v2)/T) / Z_v2
//   [2H, 2H+ND)     new_memory_v1
//   [2H+ND, 2H+2ND) new_memory_v2

#define T_INV 14.2857142857142857f   // 1/0.07
#define MOM   0.5f

#define MAX_N   100000
#define CAP     32
#define MAX_OVF 16384

// State invariant: d_count[0..N), d_ovf_cnt are ZERO at kernel_launch entry
// (zero-init at load; finish_kernel re-zeroes them). g_sum is zeroed by
// build_kernel (which runs before any accumulation).
__device__ int    d_count[MAX_N];
__device__ int    d_ell[(size_t)MAX_N * CAP];   // packed (b<<13)|k
__device__ int    d_ovf[MAX_OVF];
__device__ int    d_ovf_cnt;
__device__ double g_sum[2];                     // [0]: out_v1 raw sum, [1]: out_v2

// Counting-sort of the shared index set into ELL rows.
__global__ void __launch_bounds__(256) build_kernel(
        const int* __restrict__ idx, int H, int KP1, float invKP1)
{
    const int i = blockIdx.x * blockDim.x + threadIdx.x;
    if (i == 0) { g_sum[0] = 0.0; g_sum[1] = 0.0; }
    if (i >= H) return;

    const int r = __ldg(&idx[i]);
    // b = i / KP1 via float reciprocal + exact correction
    int b = __float2int_rz(__int2float_rn(i) * invKP1);
    int k = i - b * KP1;
    if (k < 0)         { b--; k += KP1; }
    else if (k >= KP1) { b++; k -= KP1; }

    const int packed = (b << 13) | k;
    const int pos = atomicAdd(&d_count[r], 1);
    if (pos < CAP) {
        d_ell[(size_t)r * CAP + pos] = packed;
    } else {
        const int o = atomicAdd(&d_ovf_cnt, 1);
        if (o < MAX_OVF) d_ovf[o] = packed;
    }
}

// One warp per bank row: load mem1[r] + mem2[r] once, copy them to the output
// banks, and compute every (b,k) dot pair that references row r.
__global__ void __launch_bounds__(256) main_kernel(
        const float4* __restrict__ v1,
        const float4* __restrict__ v2,
        const int*    __restrict__ idx,
        const float4* __restrict__ mem1,
        const float4* __restrict__ mem2,
        float* __restrict__ out,
        float4* __restrict__ outmem1,
        float4* __restrict__ outmem2,
        int N, int H, int KP1)
{
    const int warpsPerBlock = blockDim.x >> 5;
    const int warpInBlock   = threadIdx.x >> 5;
    const int lane          = threadIdx.x & 31;
    const int gwarp         = blockIdx.x * warpsPerBlock + warpInBlock;
    const int totalWarps    = gridDim.x * warpsPerBlock;

    float local0 = 0.0f, local1 = 0.0f;

    for (int r = gwarp; r < N; r += totalWarps) {
        // row pair: 32 float4 per bank, one per lane (coalesced 512B x2)
        const float4 m1 = mem1[(size_t)r * 32 + lane];
        const float4 m2 = mem2[(size_t)r * 32 + lane];

        // copy-through (evict-first stores; don't pollute L2)
        __stcs(&outmem1[(size_t)r * 32 + lane], m1);
        __stcs(&outmem2[(size_t)r * 32 + lane], m2);

        const int cnt = min(d_count[r], CAP);
        for (int j = 0; j < cnt; ++j) {
            const int p  = __ldg(&d_ell[(size_t)r * CAP + j]);
            const int b  = p >> 13;
            const int k  = p & 8191;
            const int d2 = b * KP1 + k;

            const float4 x1 = v1[(size_t)b * 32 + lane];  // L1-resident (64KB)
            const float4 x2 = v2[(size_t)b * 32 + lane];

            float s1 = m1.x * x2.x + m1.y * x2.y + m1.z * x2.z + m1.w * x2.w; // -> out_v2
            float s2 = m2.x * x1.x + m2.y * x1.y + m2.z * x1.z + m2.w * x1.w; // -> out_v1

            #pragma unroll
            for (int o = 16; o > 0; o >>= 1) {
                s1 += __shfl_xor_sync(0xffffffffu, s1, o);
                s2 += __shfl_xor_sync(0xffffffffu, s2, o);
            }

            if (lane == 0) {
                const float e2 = __expf(s2 * T_INV);   // out_v1
                const float e1 = __expf(s1 * T_INV);   // out_v2
                __stcs(&out[d2], e2);
                __stcs(&out[H + d2], e1);
                local0 += e2;
                local1 += e1;
            }
        }
    }

    // overflow entries (expected: none) — direct gather path
    const int novf = min(d_ovf_cnt, MAX_OVF);
    for (int o = gwarp; o < novf; o += totalWarps) {
        const int p  = d_ovf[o];
        const int b  = p >> 13;
        const int k  = p & 8191;
        const int d2 = b * KP1 + k;
        const int r  = __ldg(&idx[d2]);

        const float4 m1 = mem1[(size_t)r * 32 + lane];
        const float4 m2 = mem2[(size_t)r * 32 + lane];
        const float4 x1 = v1[(size_t)b * 32 + lane];
        const float4 x2 = v2[(size_t)b * 32 + lane];

        float s1 = m1.x * x2.x + m1.y * x2.y + m1.z * x2.z + m1.w * x2.w;
        float s2 = m2.x * x1.x + m2.y * x1.y + m2.z * x1.z + m2.w * x1.w;
        #pragma unroll
        for (int q = 16; q > 0; q >>= 1) {
            s1 += __shfl_xor_sync(0xffffffffu, s1, q);
            s2 += __shfl_xor_sync(0xffffffffu, s2, q);
        }
        if (lane == 0) {
            const float e2 = __expf(s2 * T_INV);
            const float e1 = __expf(s1 * T_INV);
            __stcs(&out[d2], e2);
            __stcs(&out[H + d2], e1);
            local0 += e2;
            local1 += e1;
        }
    }

    // block reduce -> one double atomic per block per half
    #pragma unroll
    for (int o = 16; o > 0; o >>= 1) {
        local0 += __shfl_xor_sync(0xffffffffu, local0, o);
        local1 += __shfl_xor_sync(0xffffffffu, local1, o);
    }
    __shared__ float sh0[8], sh1[8];
    if (lane == 0) { sh0[warpInBlock] = local0; sh1[warpInBlock] = local1; }
    __syncthreads();
    if (threadIdx.x == 0) {
        float a = 0.0f, b = 0.0f;
        for (int w = 0; w < warpsPerBlock; ++w) { a += sh0[w]; b += sh1[w]; }
        atomicAdd(&g_sum[0], (double)a);
        atomicAdd(&g_sum[1], (double)b);
    }
}

// Epilogue: scale score halves by 1/Z, momentum-update the B rows, and restore
// the zero-state invariant (counts, overflow counter).
__global__ void __launch_bounds__(256) finish_kernel(
        float4* __restrict__ out4,
        int Hv2,   // 2H/4
        int Hv,    // H/4
        int H, long long Nll, int N,
        const float* __restrict__ v1,
        const float* __restrict__ v2,
        const float* __restrict__ mem1,
        const float* __restrict__ mem2,
        const int*   __restrict__ y,
        float* __restrict__ outmem1,
        float* __restrict__ outmem2,
        int scaleBlocks, int B)
{
    const int bx = (int)blockIdx.x;

    if (bx < scaleBlocks) {
        const int i = bx * blockDim.x + threadIdx.x;
        if (i < Hv2) {
            const double s = (i < Hv) ? g_sum[0] : g_sum[1];
            const float scale = (float)((double)H / (s * (double)Nll));
            float4 v = out4[i];
            v.x *= scale; v.y *= scale; v.z *= scale; v.w *= scale;
            out4[i] = v;
        }
        return;
    }

    if (bx < scaleBlocks + B) {
        // momentum update: 2 (row, view) pairs per block
        const int ub    = bx - scaleBlocks;
        const int which = threadIdx.x >> 7;
        const int t     = threadIdx.x & 127;
        const int lane  = threadIdx.x & 31;
        const int w128  = (threadIdx.x >> 5) & 3;

        const float* v      = which ? v2      : v1;
        const float* mem    = which ? mem2    : mem1;
        float*       outmem = which ? outmem2 : outmem1;

        const int row = __ldg(&y[ub]);
        const float u = MOM * mem[(size_t)row * 128 + t] + (1.0f - MOM) * v[(size_t)ub * 128 + t];

        float ss = u * u;
        #pragma unroll
        for (int o = 16; o > 0; o >>= 1)
            ss += __shfl_xor_sync(0xffffffffu, ss, o);

        __shared__ float sh[2][4];
        if (lane == 0) sh[which][w128] = ss;
        __syncthreads();

        const float tot = sh[which][0] + sh[which][1] + sh[which][2] + sh[which][3];
        outmem[(size_t)row * 128 + t] = u * rsqrtf(tot);
        return;
    }

    // zero-state restore (d_count, d_ovf_cnt are NOT read inside this kernel)
    const int zb = bx - scaleBlocks - B;
    const int i  = zb * blockDim.x + threadIdx.x;
    if (i < N) d_count[i] = 0;
    if (i == 0) d_ovf_cnt = 0;
}

extern "C" void kernel_launch(void* const* d_in, const int* in_sizes, int n_in,
                              void* d_out, int out_size)
{
    const float* v1   = (const float*)d_in[0];
    const float* v2   = (const float*)d_in[1];
    const int*   idx  = (const int*)  d_in[2];
    const int*   y    = (const int*)  d_in[3];
    const float* mem1 = (const float*)d_in[4];
    const float* mem2 = (const float*)d_in[5];

    const int B   = in_sizes[3];          // 128
    const int D   = in_sizes[0] / B;      // 128
    const int KP1 = in_sizes[2] / B;      // 4097
    const int N   = in_sizes[4] / D;      // 100000
    const int H   = B * KP1;              // 524416
    const int ND  = N * D;                // 12800000

    float* out = (float*)d_out;
    float* outmem1 = out + 2 * (size_t)H;
    float* outmem2 = outmem1 + (size_t)ND;

    const float invKP1 = 1.0f / (float)KP1;

    build_kernel<<<(H + 255) / 256, 256>>>(idx, H, KP1, invKP1);

    main_kernel<<<1998, 256>>>((const float4*)v1, (const float4*)v2, idx,
                               (const float4*)mem1, (const float4*)mem2,
                               out, (float4*)outmem1, (float4*)outmem2,
                               N, H, KP1);

    const int Hv  = H / 4;
    const int Hv2 = 2 * Hv;
    const int scaleBlocks = (Hv2 + 255) / 256;
    const int zeroBlocks  = (N + 255) / 256;
    finish_kernel<<<scaleBlocks + B + zeroBlocks, 256>>>(
        (float4*)d_out, Hv2, Hv, H, (long long)N, N,
        v1, v2, mem1, mem2, y, outmem1, outmem2, scaleBlocks, B);
}